// round 6
// baseline (speedup 1.0000x reference)
#include <cuda_runtime.h>
#include <cuda_bf16.h>

#define Bn      4096
#define Dn      256
#define NEXP    4
#define NPAIR   6
#define TM      64
#define TN      64
#define KC      32
#define SPLITK  4
#define KSLAB   (Bn / SPLITK)      // 1024
#define NKL     (KSLAB / KC)       // 32 chunks per slab
#define NTILE   16
#define SPAD    72
#define STG     4
#define NCHC    128                // conv chunks per expert (32 rows each)
#define CSTRIDE (NPAIR * NTILE * 4096)   // 393216 floats per slab
#define SQBLK   192

// -------- scratch ---------------------------------------------------------
__device__ float          g_partMean[NEXP * NCHC * Dn];
__device__ __nv_bfloat16  g_z[NEXP * Bn * Dn];
__device__ float          g_partC[SPLITK * CSTRIDE];    // 6.29MB, L2-resident
__device__ float          g_bsum[SQBLK];
__device__ unsigned       g_cnt;

__constant__ int c_pi[NPAIR] = {0, 0, 0, 1, 1, 2};
__constant__ int c_pj[NPAIR] = {1, 2, 3, 2, 3, 3};

// -------- kernel 1: fp32->bf16 convert + column partial sums --------------
// grid (NCHC, NEXP) = 512 blocks, 256 threads; 32 rows x 256 cols each.
__global__ void conv_colsum_kernel(const float* __restrict__ e0,
                                   const float* __restrict__ e1,
                                   const float* __restrict__ e2,
                                   const float* __restrict__ e3) {
    if (blockIdx.x == 0 && blockIdx.y == 0 && threadIdx.x == 0) g_cnt = 0;
    int e  = blockIdx.y;
    int ch = blockIdx.x;
    const float* E = (e == 0) ? e0 : (e == 1) ? e1 : (e == 2) ? e2 : e3;
    int t  = threadIdx.x;
    int c4 = t & 63;              // float4 column (0..63)
    int rq = t >> 6;              // row phase (0..3)

    const float4* src = (const float4*)E + (size_t)(ch * 32) * 64 + c4;
    uint2* dst = (uint2*)g_z + ((size_t)e * Bn + ch * 32) * 64 + c4;

    float4 s = make_float4(0.f, 0.f, 0.f, 0.f);
#pragma unroll
    for (int r = rq; r < 32; r += 4) {
        float4 v = src[(size_t)r * 64];
        s.x += v.x; s.y += v.y; s.z += v.z; s.w += v.w;
        __nv_bfloat162 lo = __floats2bfloat162_rn(v.x, v.y);
        __nv_bfloat162 hi = __floats2bfloat162_rn(v.z, v.w);
        uint2 pk;
        pk.x = *(unsigned*)&lo; pk.y = *(unsigned*)&hi;
        dst[(size_t)r * 64] = pk;
    }
    __shared__ float4 red[4][64];
    red[rq][c4] = s;
    __syncthreads();
    if (t < 64) {
        float4 a = red[0][t], b = red[1][t], c = red[2][t], d = red[3][t];
        ((float4*)&g_partMean[(e * NCHC + ch) * Dn])[t] =
            make_float4(a.x + b.x + c.x + d.x, a.y + b.y + c.y + d.y,
                        a.z + b.z + c.z + d.z, a.w + b.w + c.w + d.w);
    }
}

// -------- kernel 2: bf16 HMMA GEMM, split-K=4, occ-3 single wave ----------
__device__ __forceinline__ void cpa16(void* smem, const void* g) {
    unsigned s = (unsigned)__cvta_generic_to_shared(smem);
    asm volatile("cp.async.cg.shared.global [%0], [%1], 16;\n" :: "r"(s), "l"(g));
}
__device__ __forceinline__ void cp_commit() {
    asm volatile("cp.async.commit_group;\n");
}
__device__ __forceinline__ void cp_wait2() {
    asm volatile("cp.async.wait_group 2;\n");
}
__device__ __forceinline__ void cp_wait0() {
    asm volatile("cp.async.wait_group 0;\n");
}
__device__ __forceinline__ void ldm_x4t(unsigned& r0, unsigned& r1,
                                        unsigned& r2, unsigned& r3,
                                        const void* p) {
    unsigned a = (unsigned)__cvta_generic_to_shared(p);
    asm volatile("ldmatrix.sync.aligned.m8n8.x4.trans.shared.b16 "
                 "{%0,%1,%2,%3}, [%4];"
                 : "=r"(r0), "=r"(r1), "=r"(r2), "=r"(r3) : "r"(a));
}
__device__ __forceinline__ void mma16816(float* c, unsigned a0, unsigned a1,
                                         unsigned a2, unsigned a3,
                                         unsigned b0, unsigned b1) {
    asm volatile("mma.sync.aligned.m16n8k16.row.col.f32.bf16.bf16.f32 "
                 "{%0,%1,%2,%3},{%4,%5,%6,%7},{%8,%9},{%0,%1,%2,%3};"
                 : "+f"(c[0]), "+f"(c[1]), "+f"(c[2]), "+f"(c[3])
                 : "r"(a0), "r"(a1), "r"(a2), "r"(a3), "r"(b0), "r"(b1));
}

__global__ __launch_bounds__(256, 3)
void gemm_kernel() {
    __shared__ __align__(16) __nv_bfloat16 SA[STG][KC][SPAD];
    __shared__ __align__(16) __nv_bfloat16 SB[STG][KC][SPAD];
    __shared__ __nv_bfloat16 tailA[TM], tailB[TN];

    int tile = blockIdx.x;
    int pair = blockIdx.y;
    int slab = blockIdx.z;
    int tm = (tile >> 2) * TM;
    int tn = (tile & 3) * TN;
    int pi = c_pi[pair], pj = c_pj[pair];
    const __nv_bfloat16* A = g_z + (size_t)pi * Bn * Dn + (size_t)slab * KSLAB * Dn + tm;
    const __nv_bfloat16* B = g_z + (size_t)pj * Bn * Dn + (size_t)slab * KSLAB * Dn + tn;

    int t    = threadIdx.x;
    int lane = t & 31;
    int w    = t >> 5;
    int wm   = (w & 3) * 16;
    int wn   = (w >> 2) * 32;

    int lk   = t >> 3;
    int lseg = (t & 7) * 8;
    size_t loff = (size_t)lk * Dn + lseg;

    int grp = lane >> 3, r = lane & 7;
    int aRow = ((grp & 2) ? 8 : 0) + r,  aCol = wm + ((grp & 1) ? 8 : 0);
    int bRow = ((grp & 1) ? 8 : 0) + r;
    int bCol0 = wn +      ((grp & 2) ? 8 : 0);
    int bCol1 = wn + 16 + ((grp & 2) ? 8 : 0);

    float acc[4][4] = {};

    auto issue = [&](int c) {
        if (c < NKL) {
            int st = c & 3;
            cpa16(&SA[st][lk][lseg], A + (size_t)c * KC * Dn + loff);
            cpa16(&SB[st][lk][lseg], B + (size_t)c * KC * Dn + loff);
        }
        cp_commit();
    };

    issue(0); issue(1); issue(2);

    // prologue, slab 0 only: rank-1 tail rows from column means
    if (slab == 0) {
        if (t < TM) {
            float s = 0.0f;
#pragma unroll 16
            for (int c = 0; c < NCHC; c++) s += g_partMean[(pi * NCHC + c) * Dn + tm + t];
            tailA[t] = __float2bfloat16(-64.0f * (s * (1.0f / (float)Bn)));
        } else if (t < TM + TN) {
            int tt = t - TM;
            float s = 0.0f;
#pragma unroll 16
            for (int c = 0; c < NCHC; c++) s += g_partMean[(pj * NCHC + c) * Dn + tn + tt];
            tailB[tt] = __float2bfloat16(64.0f * (s * (1.0f / (float)Bn)));
        }
    }

    for (int c = 0; c < NKL; ++c) {
        cp_wait2();
        __syncthreads();
        issue(c + 3);

        int st = c & 3;
#pragma unroll
        for (int s = 0; s < 2; ++s) {
            int k0 = s * 16;
            unsigned a0, a1, a2, a3;
            ldm_x4t(a0, a1, a2, a3, &SA[st][k0 + aRow][aCol]);
            unsigned b0, b1, b2, b3;
            ldm_x4t(b0, b1, b2, b3, &SB[st][k0 + bRow][bCol0]);
            unsigned b4, b5, b6, b7;
            ldm_x4t(b4, b5, b6, b7, &SB[st][k0 + bRow][bCol1]);
            mma16816(acc[0], a0, a1, a2, a3, b0, b1);
            mma16816(acc[1], a0, a1, a2, a3, b2, b3);
            mma16816(acc[2], a0, a1, a2, a3, b4, b5);
            mma16816(acc[3], a0, a1, a2, a3, b6, b7);
        }
    }

    // rank-1 tail as one k=16 mma (slab 0 only)
    if (slab == 0) {
        cp_wait0();
        __syncthreads();
        {
            int trow = t >> 4;
            int tcol = (t & 15) * 4;
            __nv_bfloat16 z = __float2bfloat16(0.0f);
            __nv_bfloat16 a0 = z, a1 = z, a2 = z, a3 = z;
            __nv_bfloat16 b0 = z, b1 = z, b2 = z, b3 = z;
            if (trow == 0) {
                a0 = tailA[tcol];     a1 = tailA[tcol + 1];
                a2 = tailA[tcol + 2]; a3 = tailA[tcol + 3];
                b0 = tailB[tcol];     b1 = tailB[tcol + 1];
                b2 = tailB[tcol + 2]; b3 = tailB[tcol + 3];
            }
            SA[0][trow][tcol] = a0; SA[0][trow][tcol + 1] = a1;
            SA[0][trow][tcol + 2] = a2; SA[0][trow][tcol + 3] = a3;
            SB[0][trow][tcol] = b0; SB[0][trow][tcol + 1] = b1;
            SB[0][trow][tcol + 2] = b2; SB[0][trow][tcol + 3] = b3;
        }
        __syncthreads();
        {
            unsigned a0, a1, a2, a3;
            ldm_x4t(a0, a1, a2, a3, &SA[0][aRow][aCol]);
            unsigned b0, b1, b2, b3;
            ldm_x4t(b0, b1, b2, b3, &SB[0][bRow][bCol0]);
            unsigned b4, b5, b6, b7;
            ldm_x4t(b4, b5, b6, b7, &SB[0][bRow][bCol1]);
            mma16816(acc[0], a0, a1, a2, a3, b0, b1);
            mma16816(acc[1], a0, a1, a2, a3, b2, b3);
            mma16816(acc[2], a0, a1, a2, a3, b4, b5);
            mma16816(acc[3], a0, a1, a2, a3, b6, b7);
        }
    }

    // store partial fragments, layout-oblivious, coalesced
    float* dst = g_partC + (size_t)slab * CSTRIDE + (((size_t)pair * NTILE + tile) << 12);
#pragma unroll
    for (int j = 0; j < 4; ++j)
#pragma unroll
        for (int i = 0; i < 4; ++i)
            dst[(j * 4 + i) * 256 + t] = acc[j][i];
}

// -------- kernel 3: combine slabs (float4), square, fused final -----------
__global__ void sq_kernel(float* __restrict__ out) {
    __shared__ float red[256];
    __shared__ int s_last;
    int t = threadIdx.x;
    const float4* pc = (const float4*)g_partC;
    const int S4 = CSTRIDE / 4;               // float4 stride per slab
    int idx0 = blockIdx.x * 512 + t;          // float4 index
    float s = 0.0f;
#pragma unroll
    for (int u = 0; u < 2; u++) {
        int idx = idx0 + u * 256;
        float4 a = pc[idx], b = pc[S4 + idx], c = pc[2 * S4 + idx], d = pc[3 * S4 + idx];
        float vx = a.x + b.x + c.x + d.x;
        float vy = a.y + b.y + c.y + d.y;
        float vz = a.z + b.z + c.z + d.z;
        float vw = a.w + b.w + c.w + d.w;
        s += vx * vx + vy * vy + vz * vz + vw * vw;
    }
#pragma unroll
    for (int o = 16; o > 0; o >>= 1) s += __shfl_xor_sync(0xffffffffu, s, o);
    if ((t & 31) == 0) red[t >> 5] = s;
    __syncthreads();
    if (t == 0) {
        float tot = 0.0f;
#pragma unroll
        for (int i = 0; i < 8; ++i) tot += red[i];
        g_bsum[blockIdx.x] = tot;
        __threadfence();
        unsigned tk = atomicAdd(&g_cnt, 1u);
        s_last = (tk == SQBLK - 1) ? 1 : 0;
    }
    __syncthreads();

    if (s_last) {
        __threadfence();
        red[t] = (t < SQBLK) ? g_bsum[t] : 0.0f;
        __syncthreads();
#pragma unroll
        for (int o = 128; o > 0; o >>= 1) {
            if (t < o) red[t] += red[t + o];
            __syncthreads();
        }
        if (t == 0) {
            const float denom = 4095.0f * 4095.0f;
            out[0] = 0.1f * (red[0] / denom) * (1.0f / (float)NPAIR);
        }
    }
}

// -------- launch ----------------------------------------------------------
extern "C" void kernel_launch(void* const* d_in, const int* in_sizes, int n_in,
                              void* d_out, int out_size) {
    const float* e0 = (const float*)d_in[0];
    const float* e1 = (const float*)d_in[1];
    const float* e2 = (const float*)d_in[2];
    const float* e3 = (const float*)d_in[3];
    float* out = (float*)d_out;

    conv_colsum_kernel<<<dim3(NCHC, NEXP), 256>>>(e0, e1, e2, e3);
    gemm_kernel<<<dim3(NTILE, NPAIR, SPLITK), 256>>>();
    sq_kernel<<<SQBLK, 256>>>(out);
}

// round 7
// speedup vs baseline: 1.0935x; 1.0935x over previous
#include <cuda_runtime.h>
#include <cuda_bf16.h>

#define Bn      4096
#define Dn      256
#define NEXP    4
#define NPAIR   6
#define TM      64
#define TN      64
#define KC      32
#define SPLITK  3
#define NTILE   16
#define SPAD    72
#define STG     4
#define NCHC    128                      // conv chunks per expert (32 rows each)
#define CSTRIDE (NPAIR * NTILE * 4096)   // 393216 floats per slab
#define SQBLK   192

// -------- scratch ---------------------------------------------------------
__device__ float          g_partMean[NEXP * NCHC * Dn];
__device__ __nv_bfloat16  g_z[NEXP * Bn * Dn];
__device__ float          g_partC[SPLITK * CSTRIDE];    // 4.7MB, L2-resident
__device__ float          g_bsum[SQBLK];
__device__ unsigned       g_cnt;

__constant__ int c_pi[NPAIR] = {0, 0, 0, 1, 1, 2};
__constant__ int c_pj[NPAIR] = {1, 2, 3, 2, 3, 3};
// uneven split-K: 44+42+42 chunks = 128 chunks = 4096 rows; grid 288 <= 296 resident
__constant__ int c_kbase[SPLITK] = {0, 44, 86};
__constant__ int c_kcnt[SPLITK]  = {44, 42, 42};

// -------- kernel 1: fp32->bf16 convert + column partial sums --------------
// Loads front-batched into registers (defeats alias-serialization -> MLP=8).
__global__ void conv_colsum_kernel(const float* __restrict__ e0,
                                   const float* __restrict__ e1,
                                   const float* __restrict__ e2,
                                   const float* __restrict__ e3) {
    if (blockIdx.x == 0 && blockIdx.y == 0 && threadIdx.x == 0) g_cnt = 0;
    int e  = blockIdx.y;
    int ch = blockIdx.x;
    const float* E = (e == 0) ? e0 : (e == 1) ? e1 : (e == 2) ? e2 : e3;
    int t  = threadIdx.x;
    int c4 = t & 63;              // float4 column (0..63)
    int rq = t >> 6;              // row phase (0..3)

    const float4* src = (const float4*)E + (size_t)(ch * 32) * 64 + c4;
    uint2* dst = (uint2*)g_z + ((size_t)e * Bn + ch * 32) * 64 + c4;

    float4 v[8];
#pragma unroll
    for (int u = 0; u < 8; u++) v[u] = src[(size_t)(rq + u * 4) * 64];

    float4 s = make_float4(0.f, 0.f, 0.f, 0.f);
#pragma unroll
    for (int u = 0; u < 8; u++) {
        s.x += v[u].x; s.y += v[u].y; s.z += v[u].z; s.w += v[u].w;
        __nv_bfloat162 lo = __floats2bfloat162_rn(v[u].x, v[u].y);
        __nv_bfloat162 hi = __floats2bfloat162_rn(v[u].z, v[u].w);
        uint2 pk;
        pk.x = *(unsigned*)&lo; pk.y = *(unsigned*)&hi;
        dst[(size_t)(rq + u * 4) * 64] = pk;
    }
    __shared__ float4 red[4][64];
    red[rq][c4] = s;
    __syncthreads();
    if (t < 64) {
        float4 a = red[0][t], b = red[1][t], c = red[2][t], d = red[3][t];
        ((float4*)&g_partMean[(e * NCHC + ch) * Dn])[t] =
            make_float4(a.x + b.x + c.x + d.x, a.y + b.y + c.y + d.y,
                        a.z + b.z + c.z + d.z, a.w + b.w + c.w + d.w);
    }
}

// -------- kernel 2: bf16 HMMA GEMM, uneven split-K=3, single wave ---------
__device__ __forceinline__ void cpa16(void* smem, const void* g) {
    unsigned s = (unsigned)__cvta_generic_to_shared(smem);
    asm volatile("cp.async.cg.shared.global [%0], [%1], 16;\n" :: "r"(s), "l"(g));
}
__device__ __forceinline__ void cp_commit() {
    asm volatile("cp.async.commit_group;\n");
}
__device__ __forceinline__ void cp_wait2() {
    asm volatile("cp.async.wait_group 2;\n");
}
__device__ __forceinline__ void cp_wait0() {
    asm volatile("cp.async.wait_group 0;\n");
}
__device__ __forceinline__ void ldm_x4t(unsigned& r0, unsigned& r1,
                                        unsigned& r2, unsigned& r3,
                                        const void* p) {
    unsigned a = (unsigned)__cvta_generic_to_shared(p);
    asm volatile("ldmatrix.sync.aligned.m8n8.x4.trans.shared.b16 "
                 "{%0,%1,%2,%3}, [%4];"
                 : "=r"(r0), "=r"(r1), "=r"(r2), "=r"(r3) : "r"(a));
}
__device__ __forceinline__ void mma16816(float* c, unsigned a0, unsigned a1,
                                         unsigned a2, unsigned a3,
                                         unsigned b0, unsigned b1) {
    asm volatile("mma.sync.aligned.m16n8k16.row.col.f32.bf16.bf16.f32 "
                 "{%0,%1,%2,%3},{%4,%5,%6,%7},{%8,%9},{%0,%1,%2,%3};"
                 : "+f"(c[0]), "+f"(c[1]), "+f"(c[2]), "+f"(c[3])
                 : "r"(a0), "r"(a1), "r"(a2), "r"(a3), "r"(b0), "r"(b1));
}

__global__ __launch_bounds__(256, 2)
void gemm_kernel() {
    __shared__ __align__(16) __nv_bfloat16 SA[STG][KC][SPAD];
    __shared__ __align__(16) __nv_bfloat16 SB[STG][KC][SPAD];
    __shared__ __nv_bfloat16 tailA[TM], tailB[TN];

    int tile = blockIdx.x;
    int pair = blockIdx.y;
    int slab = blockIdx.z;
    int kbase = c_kbase[slab];               // in KC-chunks
    int kcnt  = c_kcnt[slab];
    int tm = (tile >> 2) * TM;
    int tn = (tile & 3) * TN;
    int pi = c_pi[pair], pj = c_pj[pair];
    const __nv_bfloat16* A = g_z + (size_t)pi * Bn * Dn + (size_t)kbase * KC * Dn + tm;
    const __nv_bfloat16* B = g_z + (size_t)pj * Bn * Dn + (size_t)kbase * KC * Dn + tn;

    int t    = threadIdx.x;
    int lane = t & 31;
    int w    = t >> 5;
    int wm   = (w & 3) * 16;
    int wn   = (w >> 2) * 32;

    int lk   = t >> 3;
    int lseg = (t & 7) * 8;
    size_t loff = (size_t)lk * Dn + lseg;

    int grp = lane >> 3, r = lane & 7;
    int aRow = ((grp & 2) ? 8 : 0) + r,  aCol = wm + ((grp & 1) ? 8 : 0);
    int bRow = ((grp & 1) ? 8 : 0) + r;
    int bCol0 = wn +      ((grp & 2) ? 8 : 0);
    int bCol1 = wn + 16 + ((grp & 2) ? 8 : 0);

    float acc[4][4] = {};

    auto issue = [&](int c) {
        if (c < kcnt) {
            int st = c & 3;
            cpa16(&SA[st][lk][lseg], A + (size_t)c * KC * Dn + loff);
            cpa16(&SB[st][lk][lseg], B + (size_t)c * KC * Dn + loff);
        }
        cp_commit();
    };

    issue(0); issue(1); issue(2);

    // prologue, slab 0 only: rank-1 tail rows from column means
    if (slab == 0) {
        if (t < TM) {
            float s = 0.0f;
#pragma unroll 16
            for (int c = 0; c < NCHC; c++) s += g_partMean[(pi * NCHC + c) * Dn + tm + t];
            tailA[t] = __float2bfloat16(-64.0f * (s * (1.0f / (float)Bn)));
        } else if (t < TM + TN) {
            int tt = t - TM;
            float s = 0.0f;
#pragma unroll 16
            for (int c = 0; c < NCHC; c++) s += g_partMean[(pj * NCHC + c) * Dn + tn + tt];
            tailB[tt] = __float2bfloat16(64.0f * (s * (1.0f / (float)Bn)));
        }
    }

    for (int c = 0; c < kcnt; ++c) {
        cp_wait2();
        __syncthreads();
        issue(c + 3);

        int st = c & 3;
#pragma unroll
        for (int s = 0; s < 2; ++s) {
            int k0 = s * 16;
            unsigned a0, a1, a2, a3;
            ldm_x4t(a0, a1, a2, a3, &SA[st][k0 + aRow][aCol]);
            unsigned b0, b1, b2, b3;
            ldm_x4t(b0, b1, b2, b3, &SB[st][k0 + bRow][bCol0]);
            unsigned b4, b5, b6, b7;
            ldm_x4t(b4, b5, b6, b7, &SB[st][k0 + bRow][bCol1]);
            mma16816(acc[0], a0, a1, a2, a3, b0, b1);
            mma16816(acc[1], a0, a1, a2, a3, b2, b3);
            mma16816(acc[2], a0, a1, a2, a3, b4, b5);
            mma16816(acc[3], a0, a1, a2, a3, b6, b7);
        }
    }

    // rank-1 tail as one k=16 mma (slab 0 only)
    if (slab == 0) {
        cp_wait0();
        __syncthreads();
        {
            int trow = t >> 4;
            int tcol = (t & 15) * 4;
            __nv_bfloat16 z = __float2bfloat16(0.0f);
            __nv_bfloat16 a0 = z, a1 = z, a2 = z, a3 = z;
            __nv_bfloat16 b0 = z, b1 = z, b2 = z, b3 = z;
            if (trow == 0) {
                a0 = tailA[tcol];     a1 = tailA[tcol + 1];
                a2 = tailA[tcol + 2]; a3 = tailA[tcol + 3];
                b0 = tailB[tcol];     b1 = tailB[tcol + 1];
                b2 = tailB[tcol + 2]; b3 = tailB[tcol + 3];
            }
            SA[0][trow][tcol] = a0; SA[0][trow][tcol + 1] = a1;
            SA[0][trow][tcol + 2] = a2; SA[0][trow][tcol + 3] = a3;
            SB[0][trow][tcol] = b0; SB[0][trow][tcol + 1] = b1;
            SB[0][trow][tcol + 2] = b2; SB[0][trow][tcol + 3] = b3;
        }
        __syncthreads();
        {
            unsigned a0, a1, a2, a3;
            ldm_x4t(a0, a1, a2, a3, &SA[0][aRow][aCol]);
            unsigned b0, b1, b2, b3;
            ldm_x4t(b0, b1, b2, b3, &SB[0][bRow][bCol0]);
            unsigned b4, b5, b6, b7;
            ldm_x4t(b4, b5, b6, b7, &SB[0][bRow][bCol1]);
            mma16816(acc[0], a0, a1, a2, a3, b0, b1);
            mma16816(acc[1], a0, a1, a2, a3, b2, b3);
            mma16816(acc[2], a0, a1, a2, a3, b4, b5);
            mma16816(acc[3], a0, a1, a2, a3, b6, b7);
        }
    }

    // store partial fragments, layout-oblivious, coalesced
    float* dst = g_partC + (size_t)slab * CSTRIDE + (((size_t)pair * NTILE + tile) << 12);
#pragma unroll
    for (int j = 0; j < 4; ++j)
#pragma unroll
        for (int i = 0; i < 4; ++i)
            dst[(j * 4 + i) * 256 + t] = acc[j][i];
}

// -------- kernel 3: combine 3 slabs (float4), square, fused final ---------
__global__ void sq_kernel(float* __restrict__ out) {
    __shared__ float red[256];
    __shared__ int s_last;
    int t = threadIdx.x;
    const float4* pc = (const float4*)g_partC;
    const int S4 = CSTRIDE / 4;
    int idx0 = blockIdx.x * 512 + t;
    float s = 0.0f;
#pragma unroll
    for (int u = 0; u < 2; u++) {
        int idx = idx0 + u * 256;
        float4 a = pc[idx], b = pc[S4 + idx], c = pc[2 * S4 + idx];
        float vx = a.x + b.x + c.x;
        float vy = a.y + b.y + c.y;
        float vz = a.z + b.z + c.z;
        float vw = a.w + b.w + c.w;
        s += vx * vx + vy * vy + vz * vz + vw * vw;
    }
#pragma unroll
    for (int o = 16; o > 0; o >>= 1) s += __shfl_xor_sync(0xffffffffu, s, o);
    if ((t & 31) == 0) red[t >> 5] = s;
    __syncthreads();
    if (t == 0) {
        float tot = 0.0f;
#pragma unroll
        for (int i = 0; i < 8; ++i) tot += red[i];
        g_bsum[blockIdx.x] = tot;
        __threadfence();
        unsigned tk = atomicAdd(&g_cnt, 1u);
        s_last = (tk == SQBLK - 1) ? 1 : 0;
    }
    __syncthreads();

    if (s_last) {
        __threadfence();
        red[t] = (t < SQBLK) ? g_bsum[t] : 0.0f;
        __syncthreads();
#pragma unroll
        for (int o = 128; o > 0; o >>= 1) {
            if (t < o) red[t] += red[t + o];
            __syncthreads();
        }
        if (t == 0) {
            const float denom = 4095.0f * 4095.0f;
            out[0] = 0.1f * (red[0] / denom) * (1.0f / (float)NPAIR);
        }
    }
}

// -------- launch ----------------------------------------------------------
extern "C" void kernel_launch(void* const* d_in, const int* in_sizes, int n_in,
                              void* d_out, int out_size) {
    const float* e0 = (const float*)d_in[0];
    const float* e1 = (const float*)d_in[1];
    const float* e2 = (const float*)d_in[2];
    const float* e3 = (const float*)d_in[3];
    float* out = (float*)d_out;

    conv_colsum_kernel<<<dim3(NCHC, NEXP), 256>>>(e0, e1, e2, e3);
    gemm_kernel<<<dim3(NTILE, NPAIR, SPLITK), 256>>>();
    sq_kernel<<<SQBLK, 256>>>(out);
}